// round 4
// baseline (speedup 1.0000x reference)
#include <cuda_runtime.h>
#include <math.h>

#define NL 4
#define H  1024
#define E  2048
#define G3 3072
#define OUTN 50257
#define GI_ROWS (2 * G3)        // 6144 rows per layer (W_ih)
#define GH_UNITS (NL * 2 * G3)  // 24576 rows total (W_hh, all layers)

#define GI_BLOCKS 1536          // 4 rows/block, 2 warps per row (split-K)
#define GH_BLOCKS 3072          // 8 rows/block, warp-per-row

// Persistent scratch (__device__ globals; no allocation allowed).
__device__ float g_x[E];            // current layer input (E = 2H)
__device__ float g_gi[GI_ROWS];     // W_ih @ x + b_ih  (current layer)
__device__ float g_ghA[GH_UNITS];   // W_hh @ h + b_hh  (ALL layers, precomputed)
__device__ unsigned int g_cnt = 0;  // last-block-done counter (self-resetting)

__device__ __forceinline__ float sigmoidf(float x) {
    return 1.0f / (1.0f + expf(-x));
}

// ---------------------------------------------------------------------------
// gi work for one block: 4 rows of W_ih[l], 2 warps per row (half-row each,
// 8 independent float4 loads per lane), x staged in shared.
// ---------------------------------------------------------------------------
__device__ __forceinline__ void gi_block(
    const float* __restrict__ wih, const float* __restrict__ bih,
    const float* __restrict__ sx, int gi_blk, int l) {

    int tid  = threadIdx.x;
    int warp = tid >> 5, lane = tid & 31;

    int r0   = gi_blk * 4;
    int row  = r0 + (warp & 3);
    int half = warp >> 2;
    int d = (row >= G3) ? 1 : 0;      // same d for all 4 rows (G3 % 4 == 0)
    int j = row - d * G3;

    const float4* wi = (const float4*)(wih + ((size_t)(l * 2 + d) * G3 + j) * E)
                       + half * 256;
    const float4* xv = (const float4*)sx + half * 256;

    float s = 0.f;
    #pragma unroll
    for (int k = 0; k < 8; k++) {
        float4 w = wi[lane + k * 32];
        float4 x = xv[lane + k * 32];
        s += w.x * x.x + w.y * x.y + w.z * x.z + w.w * x.w;
    }
    #pragma unroll
    for (int o = 16; o; o >>= 1) s += __shfl_xor_sync(0xffffffffu, s, o);

    __shared__ float sp[8];
    if (lane == 0) sp[warp] = s;
    __syncthreads();

    if (tid < 4) {
        int rr = r0 + tid;
        int dd = (rr >= G3) ? 1 : 0;
        int jj = rr - dd * G3;
        g_gi[rr] = sp[tid] + sp[tid + 4] + bih[(size_t)(l * 2 + dd) * G3 + jj];
    }
}

// ---------------------------------------------------------------------------
// Tail combine for layer l (run by the LAST finished block of the launch).
// ---------------------------------------------------------------------------
__device__ __forceinline__ void combine_tail(
    const float* __restrict__ hidden, float* __restrict__ out, int l) {

    int tid = threadIdx.x;
    for (int idx = tid; idx < 2 * H; idx += 256) {
        int d = (idx >= H) ? 1 : 0;
        int j = idx - d * H;
        int base = d * G3;
        int gb = l * GI_ROWS + base;

        float ir  = g_gi[base + j],          hr = g_ghA[gb + j];
        float iz  = g_gi[base + H + j],      hz = g_ghA[gb + H + j];
        float in_ = g_gi[base + 2 * H + j],  hn = g_ghA[gb + 2 * H + j];

        float r = sigmoidf(ir + hr);
        float z = sigmoidf(iz + hz);
        float n = tanhf(in_ + r * hn);
        float hold = hidden[(size_t)(2 * l + d) * H + j];
        float hnew = (1.0f - z) * n + z * hold;

        g_x[idx] = hnew;                                  // next layer input
        out[OUTN + (size_t)(2 * l + d) * H + j] = hnew;   // new_hidden
    }
}

__device__ __forceinline__ bool last_block_done() {
    __shared__ int s_islast;
    __threadfence();
    __syncthreads();
    if (threadIdx.x == 0) {
        unsigned int n = atomicAdd(&g_cnt, 1u);
        s_islast = (n == gridDim.x - 1u) ? 1 : 0;
    }
    __syncthreads();
    return s_islast != 0;
}

// ---------------------------------------------------------------------------
// K1: ALL-layer W_hh GEMVs + layer-0 W_ih GEMV (+embed staging) + combine(0).
//   grid = GI_BLOCKS + GH_BLOCKS = 4608, 256 threads.
// ---------------------------------------------------------------------------
__global__ void __launch_bounds__(256) k1_kernel(
    const float* __restrict__ wih, const float* __restrict__ whh,
    const float* __restrict__ bih, const float* __restrict__ bhh,
    const float* __restrict__ hidden, const float* __restrict__ table,
    const int* __restrict__ feat, float* __restrict__ out) {

    __shared__ __align__(16) float sbuf[E];
    int tid  = threadIdx.x;
    int warp = tid >> 5, lane = tid & 31;

    if (blockIdx.x < GI_BLOCKS) {
        // ---- layer-0 gi: x comes straight from the embedding table ----
        size_t tb = (size_t)feat[0] * E;
        for (int i = tid; i < E; i += 256) sbuf[i] = table[tb + i];
        __syncthreads();
        gi_block(wih, bih, sbuf, blockIdx.x, 0);
    } else {
        // ---- gh: 8 rows (one warp each), all same (layer, dir) ----
        int b  = blockIdx.x - GI_BLOCKS;
        int u0 = b * 8;
        int la = u0 / GI_ROWS;
        int rem = u0 - la * GI_ROWS;
        int d = (rem >= G3) ? 1 : 0;

        const float* hp = hidden + (size_t)(2 * la + d) * H;
        for (int i = tid; i < H; i += 256) sbuf[i] = hp[i];
        __syncthreads();

        int u = u0 + warp;
        int j = rem - d * G3 + warp;
        const float4* wh = (const float4*)(whh + ((size_t)(la * 2 + d) * G3 + j) * H);
        const float4* hv = (const float4*)sbuf;

        float s = 0.f;
        #pragma unroll
        for (int k = 0; k < 8; k++) {
            float4 w = wh[lane + k * 32];
            float4 h = hv[lane + k * 32];
            s += w.x * h.x + w.y * h.y + w.z * h.z + w.w * h.w;
        }
        #pragma unroll
        for (int o = 16; o; o >>= 1) s += __shfl_xor_sync(0xffffffffu, s, o);
        if (lane == 0)
            g_ghA[u] = s + bhh[(size_t)(la * 2 + d) * G3 + j];
    }

    if (last_block_done()) {
        combine_tail(hidden, out, 0);
        __syncthreads();
        if (tid == 0) g_cnt = 0;
    }
}

// ---------------------------------------------------------------------------
// K2..K4: layer-l W_ih GEMV (+ combine(l)).  grid = GI_BLOCKS, 256 threads.
// ---------------------------------------------------------------------------
__global__ void __launch_bounds__(256) gi_kernel(
    const float* __restrict__ wih, const float* __restrict__ bih,
    const float* __restrict__ hidden, float* __restrict__ out, int l) {

    __shared__ __align__(16) float sx[E];
    int tid = threadIdx.x;
    for (int i = tid; i < E; i += 256) sx[i] = g_x[i];
    __syncthreads();

    gi_block(wih, bih, sx, blockIdx.x, l);

    if (last_block_done()) {
        combine_tail(hidden, out, l);
        __syncthreads();
        if (tid == 0) g_cnt = 0;
    }
}

// ---------------------------------------------------------------------------
// FC: warp-per-row, 4 rows/block, 128 threads (measured ~93% DRAM in R1).
// ---------------------------------------------------------------------------
__global__ void __launch_bounds__(128) fc_kernel(
    const float* __restrict__ fcw, const float* __restrict__ fcb,
    float* __restrict__ out) {

    __shared__ __align__(16) float sx[E];
    int tid = threadIdx.x;
    for (int i = tid; i < E; i += 128) sx[i] = g_x[i];
    __syncthreads();

    int warp = tid >> 5, lane = tid & 31;
    int r = blockIdx.x * 4 + warp;
    if (r >= OUTN) return;

    const float4* wr = (const float4*)(fcw + (size_t)r * E);
    const float4* xv = (const float4*)sx;

    float sum = 0.f;
    #pragma unroll
    for (int k = 0; k < 16; k++) {
        float4 w = wr[lane + k * 32];
        float4 x = xv[lane + k * 32];
        sum += w.x * x.x + w.y * x.y + w.z * x.z + w.w * x.w;
    }
    #pragma unroll
    for (int o = 16; o; o >>= 1) sum += __shfl_xor_sync(0xffffffffu, sum, o);

    if (lane == 0) out[r] = sum + fcb[r];
}

// ---------------------------------------------------------------------------
// 5 launches total: K1, gi(1..3), fc.  Graph-capturable, no allocation.
// ---------------------------------------------------------------------------
extern "C" void kernel_launch(void* const* d_in, const int* in_sizes, int n_in,
                              void* d_out, int out_size) {
    const int*   feat   = (const int*)  d_in[0];
    const float* hidden = (const float*)d_in[1];
    const float* table  = (const float*)d_in[2];
    const float* wih    = (const float*)d_in[3];
    const float* whh    = (const float*)d_in[4];
    const float* bih    = (const float*)d_in[5];
    const float* bhh    = (const float*)d_in[6];
    const float* fcw    = (const float*)d_in[7];
    const float* fcb    = (const float*)d_in[8];
    float* out = (float*)d_out;

    k1_kernel<<<GI_BLOCKS + GH_BLOCKS, 256>>>(wih, whh, bih, bhh, hidden,
                                              table, feat, out);
    for (int l = 1; l < NL; l++) {
        gi_kernel<<<GI_BLOCKS, 256>>>(wih, bih, hidden, out, l);
    }
    fc_kernel<<<(OUTN + 3) / 4, 128>>>(fcw, fcb, out);
}

// round 7
// speedup vs baseline: 1.1435x; 1.1435x over previous
#include <cuda_runtime.h>
#include <math.h>

#define NL 4
#define H  1024
#define E  2048
#define G3 3072
#define OUTN 50257
#define GI_ROWS (2 * G3)        // 6144 rows per layer (W_ih)
#define GH_UNITS (NL * 2 * G3)  // 24576 rows total (W_hh, all layers)

#define GI_BLOCKS (GI_ROWS / 4) // 1536: 4 rows/block, warp-per-row
#define GH_BLOCKS (GH_UNITS / 4)// 6144: 4 rows/block, warp-per-row

// Persistent scratch (__device__ globals; no allocation allowed).
__device__ float g_x[E];            // current layer input (E = 2H)
__device__ float g_gi[GI_ROWS];     // W_ih @ x + b_ih  (current layer)
__device__ float g_ghA[GH_UNITS];   // W_hh @ h + b_hh  (ALL layers)

__device__ __forceinline__ float sigmoidf(float x) {
    return 1.0f / (1.0f + expf(-x));
}

// ---------------------------------------------------------------------------
// gi rows for one block: 4 rows of W_ih[l], warp-per-row, 16 float4/lane,
// x already staged in shared.
// ---------------------------------------------------------------------------
__device__ __forceinline__ void gi_rows(
    const float* __restrict__ wih, const float* __restrict__ bih,
    const float* __restrict__ sx, int blk, int l) {

    int warp = threadIdx.x >> 5, lane = threadIdx.x & 31;
    int row = blk * 4 + warp;            // 0..6143
    int d = (row >= G3) ? 1 : 0;
    int j = row - d * G3;

    const float4* wi = (const float4*)(wih + ((size_t)(l * 2 + d) * G3 + j) * E);
    const float4* xv = (const float4*)sx;

    float s = 0.f;
    #pragma unroll
    for (int k = 0; k < 16; k++) {
        float4 w = wi[lane + k * 32];
        float4 x = xv[lane + k * 32];
        s += w.x * x.x + w.y * x.y + w.z * x.z + w.w * x.w;
    }
    #pragma unroll
    for (int o = 16; o; o >>= 1) s += __shfl_xor_sync(0xffffffffu, s, o);

    if (lane == 0)
        g_gi[row] = s + bih[(size_t)(l * 2 + d) * G3 + j];
}

// ---------------------------------------------------------------------------
// K1: ALL-layer W_hh GEMVs + layer-0 W_ih GEMV (x staged from embed table).
//   grid = GI_BLOCKS + GH_BLOCKS = 7680, 128 threads.  No atomics, no fences.
// ---------------------------------------------------------------------------
__global__ void __launch_bounds__(128) k1_kernel(
    const float* __restrict__ wih, const float* __restrict__ whh,
    const float* __restrict__ bih, const float* __restrict__ bhh,
    const float* __restrict__ hidden, const float* __restrict__ table,
    const int* __restrict__ feat) {

    __shared__ __align__(16) float sbuf[E];
    int tid  = threadIdx.x;
    int warp = tid >> 5, lane = tid & 31;

    if (blockIdx.x < GI_BLOCKS) {
        // ---- layer-0 gi: x straight from embedding table (L2 broadcast) ----
        size_t tb = (size_t)feat[0] * E;
        for (int i = tid; i < E; i += 128) sbuf[i] = table[tb + i];
        __syncthreads();
        gi_rows(wih, bih, sbuf, blockIdx.x, 0);
    } else {
        // ---- gh: 4 rows, warp-per-row, all same (layer, dir) ----
        int b   = blockIdx.x - GI_BLOCKS;
        int u0  = b * 4;
        int la  = u0 / GI_ROWS;
        int rem = u0 - la * GI_ROWS;
        int d   = (rem >= G3) ? 1 : 0;

        const float* hp = hidden + (size_t)(2 * la + d) * H;
        for (int i = tid; i < H; i += 128) sbuf[i] = hp[i];
        __syncthreads();

        int u = u0 + warp;
        int j = rem - d * G3 + warp;
        const float4* wh = (const float4*)(whh + ((size_t)(la * 2 + d) * G3 + j) * H);
        const float4* hv = (const float4*)sbuf;

        float s = 0.f;
        #pragma unroll
        for (int k = 0; k < 8; k++) {
            float4 w = wh[lane + k * 32];
            float4 h = hv[lane + k * 32];
            s += w.x * h.x + w.y * h.y + w.z * h.z + w.w * h.w;
        }
        #pragma unroll
        for (int o = 16; o; o >>= 1) s += __shfl_xor_sync(0xffffffffu, s, o);

        if (lane == 0)
            g_ghA[u] = s + bhh[(size_t)(la * 2 + d) * G3 + j];
    }
}

// ---------------------------------------------------------------------------
// gi layer l (l = 1..3): x staged from g_x.  grid = 1536, 128 threads.
// ---------------------------------------------------------------------------
__global__ void __launch_bounds__(128) gi_kernel(
    const float* __restrict__ wih, const float* __restrict__ bih, int l) {

    __shared__ __align__(16) float sx[E];
    int tid = threadIdx.x;
    for (int i = tid; i < E; i += 128) sx[i] = g_x[i];
    __syncthreads();

    gi_rows(wih, bih, sx, blockIdx.x, l);
}

// ---------------------------------------------------------------------------
// Combine: GRU nonlinearity for layer l.  2 blocks x 1024 threads (~1us).
// ---------------------------------------------------------------------------
__global__ void __launch_bounds__(1024) combine_kernel(
    const float* __restrict__ hidden, float* __restrict__ out, int l) {

    int idx = blockIdx.x * 1024 + threadIdx.x;   // 0 .. 2047
    int d = (idx >= H) ? 1 : 0;
    int j = idx - d * H;
    int base = d * G3;
    int gb = l * GI_ROWS + base;

    float ir  = g_gi[base + j],          hr = g_ghA[gb + j];
    float iz  = g_gi[base + H + j],      hz = g_ghA[gb + H + j];
    float in_ = g_gi[base + 2 * H + j],  hn = g_ghA[gb + 2 * H + j];

    float r = sigmoidf(ir + hr);
    float z = sigmoidf(iz + hz);
    float n = tanhf(in_ + r * hn);
    float hold = hidden[(size_t)(2 * l + d) * H + j];
    float hnew = (1.0f - z) * n + z * hold;

    g_x[idx] = hnew;                                  // next layer input
    out[OUTN + (size_t)(2 * l + d) * H + j] = hnew;   // new_hidden output
}

// ---------------------------------------------------------------------------
// FC: warp-per-row, 4 rows/block, 128 threads (proven shape).
// ---------------------------------------------------------------------------
__global__ void __launch_bounds__(128) fc_kernel(
    const float* __restrict__ fcw, const float* __restrict__ fcb,
    float* __restrict__ out) {

    __shared__ __align__(16) float sx[E];
    int tid = threadIdx.x;
    for (int i = tid; i < E; i += 128) sx[i] = g_x[i];
    __syncthreads();

    int warp = tid >> 5, lane = tid & 31;
    int r = blockIdx.x * 4 + warp;
    if (r >= OUTN) return;

    const float4* wr = (const float4*)(fcw + (size_t)r * E);
    const float4* xv = (const float4*)sx;

    float sum = 0.f;
    #pragma unroll
    for (int k = 0; k < 16; k++) {
        float4 w = wr[lane + k * 32];
        float4 x = xv[lane + k * 32];
        sum += w.x * x.x + w.y * x.y + w.z * x.z + w.w * x.w;
    }
    #pragma unroll
    for (int o = 16; o; o >>= 1) sum += __shfl_xor_sync(0xffffffffu, sum, o);

    if (lane == 0) out[r] = sum + fcb[r];
}

// ---------------------------------------------------------------------------
// 9 launches: k1, combine(0), [gi(l), combine(l)] x3, fc.
// Graph-capturable, allocation-free, no device-wide sync tricks.
// ---------------------------------------------------------------------------
extern "C" void kernel_launch(void* const* d_in, const int* in_sizes, int n_in,
                              void* d_out, int out_size) {
    const int*   feat   = (const int*)  d_in[0];
    const float* hidden = (const float*)d_in[1];
    const float* table  = (const float*)d_in[2];
    const float* wih    = (const float*)d_in[3];
    const float* whh    = (const float*)d_in[4];
    const float* bih    = (const float*)d_in[5];
    const float* bhh    = (const float*)d_in[6];
    const float* fcw    = (const float*)d_in[7];
    const float* fcb    = (const float*)d_in[8];
    float* out = (float*)d_out;

    k1_kernel<<<GI_BLOCKS + GH_BLOCKS, 128>>>(wih, whh, bih, bhh, hidden,
                                              table, feat);
    combine_kernel<<<2, 1024>>>(hidden, out, 0);
    for (int l = 1; l < NL; l++) {
        gi_kernel<<<GI_BLOCKS, 128>>>(wih, bih, l);
        combine_kernel<<<2, 1024>>>(hidden, out, l);
    }
    fc_kernel<<<(OUTN + 3) / 4, 128>>>(fcw, fcb, out);
}